// round 1
// baseline (speedup 1.0000x reference)
#include <cuda_runtime.h>
#include <cuda_bf16.h>

#define NNODES 100000
#define EPER   3200000
#define EC     2
#define IC     256
#define FF     256

// ---------------- static device scratch (no allocations allowed) ----------------
__device__ float g_xdw[NNODES * FF];            // 102.4 MB: X@W + b_dense
__device__ int   g_counts [EC * NNODES];        // per-type dst histogram
__device__ int   g_offsets[EC * (NNODES + 1)];  // exclusive scan per type
__device__ int   g_cursor [EC * NNODES];        // fill cursors
__device__ int   g_csr_src[EC * EPER];          // CSR-by-dst: source node
__device__ float g_csr_w  [EC * EPER];          // CSR-by-dst: edge weight

// ---------------- 1) SGEMM: g_xdw = X @ W + b_dense ----------------
// 128x128 tile, BK=16, 256 threads, 8x8 microtile per thread.
#define BM 128
#define BN 128
#define BK 16
__global__ __launch_bounds__(256) void sgemm_kernel(
    const float* __restrict__ X, const float* __restrict__ W,
    const float* __restrict__ bd)
{
    __shared__ float As[BK][BM];
    __shared__ float Bs[BK][BN];

    const int block_row = blockIdx.x * BM;
    const int block_col = blockIdx.y * BN;
    const int tid = threadIdx.x;
    const int tx = tid & 15;
    const int ty = tid >> 4;

    float acc[8][8];
    #pragma unroll
    for (int i = 0; i < 8; i++)
        #pragma unroll
        for (int j = 0; j < 8; j++) acc[i][j] = 0.f;

    // A-load mapping: 128 rows x 16 cols (float4 per thread, x2)
    const int arow = tid >> 2;          // 0..63
    const int acol = (tid & 3) * 4;     // 0,4,8,12
    // B-load mapping: 16 rows x 128 cols (float4 per thread, x2)
    const int brow = tid >> 5;          // 0..7
    const int bcol = (tid & 31) * 4;    // 0..124

    for (int k0 = 0; k0 < IC; k0 += BK) {
        #pragma unroll
        for (int r = 0; r < 2; r++) {
            int row = block_row + arow + r * 64;
            float4 v = make_float4(0.f, 0.f, 0.f, 0.f);
            if (row < NNODES)
                v = *(const float4*)&X[row * IC + k0 + acol];
            As[acol + 0][arow + r * 64] = v.x;
            As[acol + 1][arow + r * 64] = v.y;
            As[acol + 2][arow + r * 64] = v.z;
            As[acol + 3][arow + r * 64] = v.w;
        }
        #pragma unroll
        for (int r = 0; r < 2; r++) {
            int row = k0 + brow + r * 8;
            float4 v = *(const float4*)&W[row * FF + block_col + bcol];
            *(float4*)&Bs[brow + r * 8][bcol] = v;
        }
        __syncthreads();

        #pragma unroll
        for (int k = 0; k < BK; k++) {
            float a[8], b[8];
            #pragma unroll
            for (int i = 0; i < 8; i++) a[i] = As[k][ty * 8 + i];
            #pragma unroll
            for (int j = 0; j < 8; j++) b[j] = Bs[k][tx * 8 + j];
            #pragma unroll
            for (int i = 0; i < 8; i++)
                #pragma unroll
                for (int j = 0; j < 8; j++)
                    acc[i][j] = fmaf(a[i], b[j], acc[i][j]);
        }
        __syncthreads();
    }

    #pragma unroll
    for (int i = 0; i < 8; i++) {
        int row = block_row + ty * 8 + i;
        if (row >= NNODES) continue;
        #pragma unroll
        for (int j = 0; j < 8; j += 4) {
            int col = block_col + tx * 8 + j;
            float4 v;
            v.x = acc[i][j + 0] + bd[col + 0];
            v.y = acc[i][j + 1] + bd[col + 1];
            v.z = acc[i][j + 2] + bd[col + 2];
            v.w = acc[i][j + 3] + bd[col + 3];
            *(float4*)&g_xdw[row * FF + col] = v;
        }
    }
}

// ---------------- 2) CSR build ----------------
__global__ void zero_counts_kernel()
{
    int i = blockIdx.x * blockDim.x + threadIdx.x;
    if (i < EC * NNODES) g_counts[i] = 0;
}

__global__ void hist_kernel(const int* __restrict__ edge_dst)
{
    int i = blockIdx.x * blockDim.x + threadIdx.x;
    if (i < EC * EPER) {
        int e = i / EPER;
        int d = edge_dst[i];
        atomicAdd(&g_counts[e * NNODES + d], 1);
    }
}

// Sequential-chunk exclusive scan: one block of 1024 threads per edge type.
__global__ __launch_bounds__(1024) void scan_kernel()
{
    const int e = blockIdx.x;
    __shared__ int sdata[1024];
    __shared__ int carry;
    if (threadIdx.x == 0) carry = 0;
    __syncthreads();

    for (int base = 0; base < NNODES; base += 1024) {
        int idx = base + threadIdx.x;
        int v = (idx < NNODES) ? g_counts[e * NNODES + idx] : 0;
        sdata[threadIdx.x] = v;
        __syncthreads();
        // Hillis-Steele inclusive scan
        #pragma unroll
        for (int off = 1; off < 1024; off <<= 1) {
            int t = (threadIdx.x >= off) ? sdata[threadIdx.x - off] : 0;
            __syncthreads();
            sdata[threadIdx.x] += t;
            __syncthreads();
        }
        int incl = sdata[threadIdx.x];
        int excl = incl - v + carry;
        if (idx < NNODES) {
            g_offsets[e * (NNODES + 1) + idx] = excl;
            g_cursor [e * NNODES + idx]       = excl;
        }
        __syncthreads();
        if (threadIdx.x == 1023) carry += sdata[1023];
        __syncthreads();
    }
    if (threadIdx.x == 0) g_offsets[e * (NNODES + 1) + NNODES] = carry;
}

__global__ void fill_kernel(const int* __restrict__ edge_src,
                            const int* __restrict__ edge_dst,
                            const float* __restrict__ edge_w)
{
    int i = blockIdx.x * blockDim.x + threadIdx.x;
    if (i < EC * EPER) {
        int e = i / EPER;
        int d = edge_dst[i];
        int pos = atomicAdd(&g_cursor[e * NNODES + d], 1);
        g_csr_src[e * EPER + pos] = edge_src[i];
        g_csr_w  [e * EPER + pos] = edge_w[i];
    }
}

// ---------------- 3) atomic-free aggregation ----------------
// One 64-thread block per (node, edge-type); each thread owns 4 channels.
__global__ __launch_bounds__(64) void aggregate_kernel(
    const float* __restrict__ bias, float* __restrict__ out)
{
    const int node = blockIdx.x;
    const int e    = blockIdx.y;
    const int t    = threadIdx.x;   // 0..63

    const int beg = g_offsets[e * (NNODES + 1) + node];
    const int end = g_offsets[e * (NNODES + 1) + node + 1];
    const int base = e * EPER;

    const float4* __restrict__ xdw4 = (const float4*)g_xdw;

    float4 acc = make_float4(0.f, 0.f, 0.f, 0.f);

    int i = beg;
    for (; i + 1 < end; i += 2) {
        int   s0 = g_csr_src[base + i];
        int   s1 = g_csr_src[base + i + 1];
        float w0 = g_csr_w[base + i];
        float w1 = g_csr_w[base + i + 1];
        float4 v0 = xdw4[s0 * (FF / 4) + t];
        float4 v1 = xdw4[s1 * (FF / 4) + t];
        acc.x = fmaf(w0, v0.x, acc.x);
        acc.y = fmaf(w0, v0.y, acc.y);
        acc.z = fmaf(w0, v0.z, acc.z);
        acc.w = fmaf(w0, v0.w, acc.w);
        acc.x = fmaf(w1, v1.x, acc.x);
        acc.y = fmaf(w1, v1.y, acc.y);
        acc.z = fmaf(w1, v1.z, acc.z);
        acc.w = fmaf(w1, v1.w, acc.w);
    }
    if (i < end) {
        int   s0 = g_csr_src[base + i];
        float w0 = g_csr_w[base + i];
        float4 v0 = xdw4[s0 * (FF / 4) + t];
        acc.x = fmaf(w0, v0.x, acc.x);
        acc.y = fmaf(w0, v0.y, acc.y);
        acc.z = fmaf(w0, v0.z, acc.z);
        acc.w = fmaf(w0, v0.w, acc.w);
    }

    const int col = e * FF + 4 * t;
    float4 b = *(const float4*)&bias[col];
    acc.x = fmaxf(acc.x + b.x, 0.f);
    acc.y = fmaxf(acc.y + b.y, 0.f);
    acc.z = fmaxf(acc.z + b.z, 0.f);
    acc.w = fmaxf(acc.w + b.w, 0.f);

    *(float4*)&out[node * (EC * FF) + col] = acc;
}

// ---------------- launch ----------------
extern "C" void kernel_launch(void* const* d_in, const int* in_sizes, int n_in,
                              void* d_out, int out_size)
{
    const float* x        = (const float*)d_in[0];
    const int*   edge_src = (const int*)  d_in[1];
    const int*   edge_dst = (const int*)  d_in[2];
    const float* edge_w   = (const float*)d_in[3];
    const float* W        = (const float*)d_in[4];
    const float* b_dense  = (const float*)d_in[5];
    const float* bias     = (const float*)d_in[6];
    float* out = (float*)d_out;

    // GEMM: xdw = X @ W + b_dense
    dim3 ggrid((NNODES + BM - 1) / BM, FF / BN);
    sgemm_kernel<<<ggrid, 256>>>(x, W, b_dense);

    // CSR build
    int nz = (EC * NNODES + 255) / 256;
    zero_counts_kernel<<<nz, 256>>>();
    int ne = (EC * EPER + 255) / 256;
    hist_kernel<<<ne, 256>>>(edge_dst);
    scan_kernel<<<EC, 1024>>>();
    fill_kernel<<<ne, 256>>>(edge_src, edge_dst, edge_w);

    // Aggregate + bias + ReLU
    dim3 agrid(NNODES, EC);
    aggregate_kernel<<<agrid, 64>>>(bias, out);
}

// round 2
// speedup vs baseline: 1.4781x; 1.4781x over previous
#include <cuda_runtime.h>
#include <cuda_fp16.h>

#define NNODES 100000
#define EPER   3200000
#define EC     2
#define IC     256
#define FF     256
#define NB     ((NNODES + 2047) / 2048)   // 49 scan blocks per edge type

// ---------------- static device scratch ----------------
__device__ __half g_xdw_h[NNODES * FF];          // 51.2 MB fp16 X@W + b
__device__ int    g_counts [EC * NNODES];
__device__ int    g_offsets[EC * (NNODES + 1)];
__device__ int    g_cursor [EC * NNODES];
__device__ int    g_partial[EC * 64];            // per-block partial sums for scan
__device__ int    g_csr_src[EC * EPER];
__device__ float  g_csr_w  [EC * EPER];

// ---------------- 1) SGEMM: g_xdw_h = half(X @ W + b_dense) ----------------
#define BM 128
#define BN 128
#define BK 16
__global__ __launch_bounds__(256) void sgemm_kernel(
    const float* __restrict__ X, const float* __restrict__ W,
    const float* __restrict__ bd)
{
    __shared__ float As[BK][BM];
    __shared__ float Bs[BK][BN];

    const int block_row = blockIdx.x * BM;
    const int block_col = blockIdx.y * BN;
    const int tid = threadIdx.x;
    const int tx = tid & 15;
    const int ty = tid >> 4;

    float acc[8][8];
    #pragma unroll
    for (int i = 0; i < 8; i++)
        #pragma unroll
        for (int j = 0; j < 8; j++) acc[i][j] = 0.f;

    const int arow = tid >> 2;
    const int acol = (tid & 3) * 4;
    const int brow = tid >> 5;
    const int bcol = (tid & 31) * 4;

    for (int k0 = 0; k0 < IC; k0 += BK) {
        #pragma unroll
        for (int r = 0; r < 2; r++) {
            int row = block_row + arow + r * 64;
            float4 v = make_float4(0.f, 0.f, 0.f, 0.f);
            if (row < NNODES)
                v = *(const float4*)&X[row * IC + k0 + acol];
            As[acol + 0][arow + r * 64] = v.x;
            As[acol + 1][arow + r * 64] = v.y;
            As[acol + 2][arow + r * 64] = v.z;
            As[acol + 3][arow + r * 64] = v.w;
        }
        #pragma unroll
        for (int r = 0; r < 2; r++) {
            int row = k0 + brow + r * 8;
            *(float4*)&Bs[brow + r * 8][bcol] =
                *(const float4*)&W[row * FF + block_col + bcol];
        }
        __syncthreads();

        #pragma unroll
        for (int k = 0; k < BK; k++) {
            float a[8], b[8];
            #pragma unroll
            for (int i = 0; i < 8; i++) a[i] = As[k][ty * 8 + i];
            #pragma unroll
            for (int j = 0; j < 8; j++) b[j] = Bs[k][tx * 8 + j];
            #pragma unroll
            for (int i = 0; i < 8; i++)
                #pragma unroll
                for (int j = 0; j < 8; j++)
                    acc[i][j] = fmaf(a[i], b[j], acc[i][j]);
        }
        __syncthreads();
    }

    #pragma unroll
    for (int i = 0; i < 8; i++) {
        int row = block_row + ty * 8 + i;
        if (row >= NNODES) continue;
        int col = block_col + tx * 8;
        __half h[8];
        #pragma unroll
        for (int j = 0; j < 8; j++)
            h[j] = __float2half_rn(acc[i][j] + bd[col + j]);
        *(uint4*)&g_xdw_h[row * FF + col] = *(uint4*)h;   // 16B store of 8 halves
    }
}

// ---------------- 2) CSR build ----------------
__global__ void zero_counts_kernel()
{
    int i = blockIdx.x * blockDim.x + threadIdx.x;
    if (i < EC * NNODES) g_counts[i] = 0;
}

__global__ void hist_kernel(const int* __restrict__ edge_dst)
{
    int i = blockIdx.x * blockDim.x + threadIdx.x;
    if (i < EC * EPER) {
        int e = i / EPER;
        atomicAdd(&g_counts[e * NNODES + edge_dst[i]], 1);
    }
}

// --- scan stage A: per-block (2048 elems) sums ---
__global__ __launch_bounds__(256) void scan_reduce_kernel()
{
    const int e   = blockIdx.y;
    const int blk = blockIdx.x;
    const int t   = threadIdx.x;
    int s = 0;
    #pragma unroll
    for (int k = 0; k < 8; k++) {
        int idx = blk * 2048 + k * 256 + t;
        if (idx < NNODES) s += g_counts[e * NNODES + idx];
    }
    // warp reduce
    #pragma unroll
    for (int off = 16; off > 0; off >>= 1)
        s += __shfl_down_sync(0xffffffffu, s, off);
    __shared__ int wsum[8];
    if ((t & 31) == 0) wsum[t >> 5] = s;
    __syncthreads();
    if (t == 0) {
        int tot = 0;
        #pragma unroll
        for (int w = 0; w < 8; w++) tot += wsum[w];
        g_partial[e * 64 + blk] = tot;
    }
}

// --- scan stage B: exclusive scan of NB partials per edge type ---
__global__ void scan_top_kernel()
{
    int e = threadIdx.x;
    if (e < EC) {
        int run = 0;
        for (int b = 0; b < NB; b++) {
            int v = g_partial[e * 64 + b];
            g_partial[e * 64 + b] = run;
            run += v;
        }
        g_offsets[e * (NNODES + 1) + NNODES] = run;
    }
}

// --- scan stage C: downsweep, write offsets + cursors ---
__global__ __launch_bounds__(256) void scan_down_kernel()
{
    const int e   = blockIdx.y;
    const int blk = blockIdx.x;
    const int t   = threadIdx.x;
    const int lane = t & 31, wid = t >> 5;

    __shared__ int sv[2048];
    __shared__ int wtot[8];

    #pragma unroll
    for (int k = 0; k < 8; k++) {
        int idx = blk * 2048 + k * 256 + t;
        sv[k * 256 + t] = (idx < NNODES) ? g_counts[e * NNODES + idx] : 0;
    }
    __syncthreads();

    // thread-local sum over its contiguous 8 elems
    int base = t * 8;
    int lsum = 0;
    #pragma unroll
    for (int k = 0; k < 8; k++) lsum += sv[base + k];

    // warp inclusive scan of thread sums
    int incl = lsum;
    #pragma unroll
    for (int off = 1; off < 32; off <<= 1) {
        int n = __shfl_up_sync(0xffffffffu, incl, off);
        if (lane >= off) incl += n;
    }
    if (lane == 31) wtot[wid] = incl;
    __syncthreads();
    if (wid == 0 && lane < 8) {
        int x = wtot[lane];
        int wi = x;
        #pragma unroll
        for (int off = 1; off < 8; off <<= 1) {
            int n = __shfl_up_sync(0xffu, wi, off);
            if (lane >= off) wi += n;
        }
        wtot[lane] = wi - x;    // exclusive
    }
    __syncthreads();

    int run = g_partial[e * 64 + blk] + wtot[wid] + (incl - lsum);
    #pragma unroll
    for (int k = 0; k < 8; k++) {
        int idx = blk * 2048 + base + k;
        if (idx < NNODES) {
            g_offsets[e * (NNODES + 1) + idx] = run;
            g_cursor [e * NNODES + idx]       = run;
            run += sv[base + k];
        }
    }
}

__global__ void fill_kernel(const int* __restrict__ edge_src,
                            const int* __restrict__ edge_dst,
                            const float* __restrict__ edge_w)
{
    int i = blockIdx.x * blockDim.x + threadIdx.x;
    if (i < EC * EPER) {
        int e = i / EPER;
        int pos = atomicAdd(&g_cursor[e * NNODES + edge_dst[i]], 1);
        g_csr_src[e * EPER + pos] = edge_src[i];
        g_csr_w  [e * EPER + pos] = edge_w[i];
    }
}

// ---------------- 3) aggregation: warp per (node, edge-type), fp16 gather ----------------
__global__ __launch_bounds__(128) void aggregate_kernel(
    const float* __restrict__ bias, float* __restrict__ out)
{
    const int warp = threadIdx.x >> 5;
    const int lane = threadIdx.x & 31;
    const int node = blockIdx.x * 4 + warp;
    const int e    = blockIdx.y;
    if (node >= NNODES) return;

    const int beg  = g_offsets[e * (NNODES + 1) + node];
    const int end  = g_offsets[e * (NNODES + 1) + node + 1];
    const int base = e * EPER;

    const uint4* __restrict__ row4 = (const uint4*)g_xdw_h;   // 32 uint4 per row

    float a[8];
    #pragma unroll
    for (int j = 0; j < 8; j++) a[j] = 0.f;

    int i = beg;
    for (; i + 1 < end; i += 2) {
        int   s0 = g_csr_src[base + i];
        int   s1 = g_csr_src[base + i + 1];
        float w0 = g_csr_w[base + i];
        float w1 = g_csr_w[base + i + 1];
        uint4 h0 = row4[s0 * 32 + lane];
        uint4 h1 = row4[s1 * 32 + lane];
        const __half2* p0 = (const __half2*)&h0;
        const __half2* p1 = (const __half2*)&h1;
        #pragma unroll
        for (int q = 0; q < 4; q++) {
            float2 f0 = __half22float2(p0[q]);
            float2 f1 = __half22float2(p1[q]);
            a[2*q+0] = fmaf(w0, f0.x, a[2*q+0]);
            a[2*q+1] = fmaf(w0, f0.y, a[2*q+1]);
            a[2*q+0] = fmaf(w1, f1.x, a[2*q+0]);
            a[2*q+1] = fmaf(w1, f1.y, a[2*q+1]);
        }
    }
    if (i < end) {
        int   s0 = g_csr_src[base + i];
        float w0 = g_csr_w[base + i];
        uint4 h0 = row4[s0 * 32 + lane];
        const __half2* p0 = (const __half2*)&h0;
        #pragma unroll
        for (int q = 0; q < 4; q++) {
            float2 f0 = __half22float2(p0[q]);
            a[2*q+0] = fmaf(w0, f0.x, a[2*q+0]);
            a[2*q+1] = fmaf(w0, f0.y, a[2*q+1]);
        }
    }

    const int col = e * FF + lane * 8;
    float4 b0 = *(const float4*)&bias[col];
    float4 b1 = *(const float4*)&bias[col + 4];
    float4 o0, o1;
    o0.x = fmaxf(a[0] + b0.x, 0.f);
    o0.y = fmaxf(a[1] + b0.y, 0.f);
    o0.z = fmaxf(a[2] + b0.z, 0.f);
    o0.w = fmaxf(a[3] + b0.w, 0.f);
    o1.x = fmaxf(a[4] + b1.x, 0.f);
    o1.y = fmaxf(a[5] + b1.y, 0.f);
    o1.z = fmaxf(a[6] + b1.z, 0.f);
    o1.w = fmaxf(a[7] + b1.w, 0.f);
    *(float4*)&out[node * (EC * FF) + col]     = o0;
    *(float4*)&out[node * (EC * FF) + col + 4] = o1;
}

// ---------------- launch ----------------
extern "C" void kernel_launch(void* const* d_in, const int* in_sizes, int n_in,
                              void* d_out, int out_size)
{
    const float* x        = (const float*)d_in[0];
    const int*   edge_src = (const int*)  d_in[1];
    const int*   edge_dst = (const int*)  d_in[2];
    const float* edge_w   = (const float*)d_in[3];
    const float* W        = (const float*)d_in[4];
    const float* b_dense  = (const float*)d_in[5];
    const float* bias     = (const float*)d_in[6];
    float* out = (float*)d_out;

    dim3 ggrid((NNODES + BM - 1) / BM, FF / BN);
    sgemm_kernel<<<ggrid, 256>>>(x, W, b_dense);

    int nz = (EC * NNODES + 255) / 256;
    zero_counts_kernel<<<nz, 256>>>();
    int ne = (EC * EPER + 255) / 256;
    hist_kernel<<<ne, 256>>>(edge_dst);

    dim3 sgrid(NB, EC);
    scan_reduce_kernel<<<sgrid, 256>>>();
    scan_top_kernel<<<1, 32>>>();
    scan_down_kernel<<<sgrid, 256>>>();

    fill_kernel<<<ne, 256>>>(edge_src, edge_dst, edge_w);

    dim3 agrid((NNODES + 3) / 4, EC);
    aggregate_kernel<<<agrid, 128>>>(bias, out);
}